// round 17
// baseline (speedup 1.0000x reference)
#include <cuda_runtime.h>
#include <cuda_bf16.h>
#include <cstdint>

// Problem constants
#define D_MODEL 512
#define S_LEN   2048
#define NB      2
#define NH      8
#define DK      64
#define MROWS   (NB * S_LEN)    // 4096
#define BHCNT   (NB * NH)       // 16
#define PAIRS   (DK / 2)        // 32 u32 per head row
#define DPAIRS  (D_MODEL / 2)   // 256 u32 per full row

// --------------------------------------------------------------------------
// Pre-split bf16 hi/lo planes (pair-packed u32 = [bf16 even | bf16 odd])
// --------------------------------------------------------------------------
__device__ uint32_t g_XAh[3][MROWS * DPAIRS];   // q/k/v activations
__device__ uint32_t g_XAl[3][MROWS * DPAIRS];
__device__ uint32_t g_Wh[4][D_MODEL * DPAIRS];  // w_q w_k w_v w_o
__device__ uint32_t g_Wl[4][D_MODEL * DPAIRS];
__device__ uint32_t g_Oh[MROWS * DPAIRS];       // attention output planes
__device__ uint32_t g_Ol[MROWS * DPAIRS];
// head-split projection outputs
__device__ uint32_t g_Qh[BHCNT * S_LEN * PAIRS];
__device__ uint32_t g_Ql[BHCNT * S_LEN * PAIRS];
__device__ uint32_t g_Kh[BHCNT * S_LEN * PAIRS];
__device__ uint32_t g_Kl[BHCNT * S_LEN * PAIRS];
__device__ uint32_t g_Vh[BHCNT * S_LEN * PAIRS];
__device__ uint32_t g_Vl[BHCNT * S_LEN * PAIRS];

// ===========================================================================
// Helpers (plain sm_75/80 PTX, no 'a'-features)
// ===========================================================================
__device__ __forceinline__ void mma_bf16(float* d, const uint32_t* a, const uint32_t* b)
{
    asm volatile(
        "mma.sync.aligned.m16n8k16.row.col.f32.bf16.bf16.f32 "
        "{%0,%1,%2,%3}, {%4,%5,%6,%7}, {%8,%9}, {%0,%1,%2,%3};"
        : "+f"(d[0]), "+f"(d[1]), "+f"(d[2]), "+f"(d[3])
        : "r"(a[0]), "r"(a[1]), "r"(a[2]), "r"(a[3]), "r"(b[0]), "r"(b[1]));
}

__device__ __forceinline__ void ldsm_x4(uint32_t* r, uint32_t addr)
{
    asm volatile("ldmatrix.sync.aligned.m8n8.x4.shared.b16 {%0,%1,%2,%3}, [%4];"
                 : "=r"(r[0]), "=r"(r[1]), "=r"(r[2]), "=r"(r[3]) : "r"(addr));
}
__device__ __forceinline__ void ldsm_x4_trans(uint32_t* r, uint32_t addr)
{
    asm volatile("ldmatrix.sync.aligned.m8n8.x4.trans.shared.b16 {%0,%1,%2,%3}, [%4];"
                 : "=r"(r[0]), "=r"(r[1]), "=r"(r[2]), "=r"(r[3]) : "r"(addr));
}

__device__ __forceinline__ uint32_t smem_u32(const void* p) {
    uint32_t addr;
    asm("{ .reg .u64 tmp; cvta.to.shared.u64 tmp, %1; cvt.u32.u64 %0, tmp; }"
        : "=r"(addr) : "l"(p));
    return addr;
}

__device__ __forceinline__ void cp_async16(uint32_t dst, const void* src) {
    asm volatile("cp.async.cg.shared.global [%0], [%1], 16;" :: "r"(dst), "l"(src));
}
__device__ __forceinline__ void cp_commit() {
    asm volatile("cp.async.commit_group;" ::: "memory");
}
template <int N>
__device__ __forceinline__ void cp_wait() {
    asm volatile("cp.async.wait_group %0;" :: "n"(N) : "memory");
}

__device__ __forceinline__ void split_bf16x2(float x, float y, uint32_t& h, uint32_t& l)
{
    __nv_bfloat162 hb = __floats2bfloat162_rn(x, y);
    h = *reinterpret_cast<uint32_t*>(&hb);
    float rx = x - __bfloat162float(hb.x);
    float ry = y - __bfloat162float(hb.y);
    __nv_bfloat162 lb = __floats2bfloat162_rn(rx, ry);
    l = *reinterpret_cast<uint32_t*>(&lb);
}

// ===========================================================================
// Pre-split pass: fp32 -> bf16 hi/lo planes. One pair per thread.
// ===========================================================================
__global__ __launch_bounds__(256) void split_inputs(
    const float* __restrict__ q, const float* __restrict__ k,
    const float* __restrict__ v,
    const float* __restrict__ wq, const float* __restrict__ wk,
    const float* __restrict__ wv, const float* __restrict__ wo)
{
    const int z = blockIdx.y;
    const int idx = blockIdx.x * 256 + threadIdx.x;
    const float* src; uint32_t* dh; uint32_t* dl; int np;
    switch (z) {
        case 0: src = q;  dh = g_XAh[0]; dl = g_XAl[0]; np = MROWS * DPAIRS; break;
        case 1: src = k;  dh = g_XAh[1]; dl = g_XAl[1]; np = MROWS * DPAIRS; break;
        case 2: src = v;  dh = g_XAh[2]; dl = g_XAl[2]; np = MROWS * DPAIRS; break;
        case 3: src = wq; dh = g_Wh[0];  dl = g_Wl[0];  np = D_MODEL * DPAIRS; break;
        case 4: src = wk; dh = g_Wh[1];  dl = g_Wl[1];  np = D_MODEL * DPAIRS; break;
        case 5: src = wv; dh = g_Wh[2];  dl = g_Wl[2];  np = D_MODEL * DPAIRS; break;
        default: src = wo; dh = g_Wh[3]; dl = g_Wl[3];  np = D_MODEL * DPAIRS; break;
    }
    if (idx >= np) return;
    const float2 vv = ((const float2*)src)[idx];
    uint32_t h, l;
    split_bf16x2(vv.x, vv.y, h, l);
    dh[idx] = h; dl[idx] = l;
}

// ===========================================================================
// 3xBF16 GEMM — byte-identical to the verified R14/R16 kernel.
//   512 threads, CTA 128x128, 16 warps (4m x 4n), warp 32x32, k-chunk 32.
// SMEM: 2 bufs x 4 planes x [128][20] u32 = 81,920 B
// ===========================================================================
#define GROW  20
#define GPLN  (128 * GROW)          // 2560 u32 per plane
#define GBUF  (4 * GPLN)            // 10240 u32 per buffer

__global__ __launch_bounds__(512, 1) void bf16_gemm(
    const float* __restrict__ bq_, const float* __restrict__ bk_,
    const float* __restrict__ bv_, float* __restrict__ outp, int mode)
{
    extern __shared__ __align__(16) uint32_t smg[];
    const uint32_t sb = smem_u32(smg);

    const uint32_t *Ah, *Al, *Bh, *Bl;
    const float* bias; float scale = 1.0f;
    uint32_t* dsth = nullptr; uint32_t* dstl = nullptr;
    if (mode == 0) {
        const int z = blockIdx.z;
        Ah = g_XAh[z]; Al = g_XAl[z]; Bh = g_Wh[z]; Bl = g_Wl[z];
        if (z == 0)      { bias = bq_; dsth = g_Qh; dstl = g_Ql; scale = 0.125f; }
        else if (z == 1) { bias = bk_; dsth = g_Kh; dstl = g_Kl; }
        else             { bias = bv_; dsth = g_Vh; dstl = g_Vl; }
    } else {
        Ah = g_Oh; Al = g_Ol; Bh = g_Wh[3]; Bl = g_Wl[3]; bias = bq_;
    }

    const int tid = threadIdx.x;
    const int wid = tid >> 5, lid = tid & 31;
    const int g = lid >> 2, tg = lid & 3;
    const int mwarp = wid & 3, nwarp = wid >> 2;     // 4 x 4 warp grid
    const int m0 = blockIdx.y * 128, n0 = blockIdx.x * 128;

    auto load_chunk = [&](int buf, int chunk) {
        const int kcol = chunk * 16;
#pragma unroll
        for (int t = 0; t < 4; t++) {
            const int f = tid + 512 * t;
            const int isB = f >> 10;
            const int rem = f & 1023;
            const int plane = rem >> 9;
            const int r2 = rem & 511;
            const int r = r2 >> 2, cc = r2 & 3;
            const uint32_t* base = isB ? (plane ? Bl : Bh) : (plane ? Al : Ah);
            const uint32_t* src = base + (size_t)((isB ? n0 : m0) + r) * DPAIRS + kcol + cc * 4;
            const uint32_t doff = (uint32_t)(buf * GBUF + (isB * 2 + plane) * GPLN + r * GROW + cc * 4);
            cp_async16(sb + doff * 4u, src);
        }
    };

    float acc[2][4][4];
#pragma unroll
    for (int i = 0; i < 2; i++)
#pragma unroll
        for (int j = 0; j < 4; j++)
#pragma unroll
            for (int e = 0; e < 4; e++) acc[i][j][e] = 0.0f;

    load_chunk(0, 0);
    cp_commit();

    for (int c = 0; c < 16; c++) {
        const int buf = c & 1;
        if (c < 15) {
            load_chunk(buf ^ 1, c + 1);
            cp_commit();
            cp_wait<1>();
        } else {
            cp_wait<0>();
        }
        __syncthreads();

        const uint32_t abase = sb + (uint32_t)(buf * GBUF) * 4u;
#pragma unroll
        for (int ks = 0; ks < 2; ks++) {
            const uint32_t kb = (uint32_t)((lid >> 4) * 16 + ks * 32);
            uint32_t ah[2][4], al[2][4];
#pragma unroll
            for (int i = 0; i < 2; i++) {
                const uint32_t row = (uint32_t)(mwarp * 32 + i * 16 + (lid & 15));
                ldsm_x4(ah[i], abase + row * (GROW * 4) + kb);
                ldsm_x4(al[i], abase + GPLN * 4 + row * (GROW * 4) + kb);
            }
            uint32_t bh[4][2], bl[4][2];
            const uint32_t kbB = (uint32_t)(((lid >> 3) & 1) * 16 + ks * 32);
#pragma unroll
            for (int jp = 0; jp < 2; jp++) {
                const uint32_t row = (uint32_t)(nwarp * 32 + jp * 16 + ((lid >> 4) & 1) * 8 + (lid & 7));
                uint32_t r4[4];
                ldsm_x4(r4, abase + 2 * GPLN * 4 + row * (GROW * 4) + kbB);
                bh[jp * 2][0] = r4[0]; bh[jp * 2][1] = r4[1];
                bh[jp * 2 + 1][0] = r4[2]; bh[jp * 2 + 1][1] = r4[3];
                ldsm_x4(r4, abase + 3 * GPLN * 4 + row * (GROW * 4) + kbB);
                bl[jp * 2][0] = r4[0]; bl[jp * 2][1] = r4[1];
                bl[jp * 2 + 1][0] = r4[2]; bl[jp * 2 + 1][1] = r4[3];
            }
#pragma unroll
            for (int i = 0; i < 2; i++)
#pragma unroll
                for (int j = 0; j < 4; j++) mma_bf16(acc[i][j], ah[i], bh[j]);
#pragma unroll
            for (int i = 0; i < 2; i++)
#pragma unroll
                for (int j = 0; j < 4; j++) mma_bf16(acc[i][j], al[i], bh[j]);
#pragma unroll
            for (int i = 0; i < 2; i++)
#pragma unroll
                for (int j = 0; j < 4; j++) mma_bf16(acc[i][j], ah[i], bl[j]);
        }
        __syncthreads();
    }

    // ---- epilogue ----
#pragma unroll
    for (int j = 0; j < 4; j++) {
        const int n = n0 + nwarp * 32 + j * 8 + 2 * tg;      // even column
        const float bv0 = __ldg(&bias[n]), bv1 = __ldg(&bias[n + 1]);
#pragma unroll
        for (int i = 0; i < 2; i++) {
            const int mA = m0 + mwarp * 32 + i * 16 + g;
            const int mB = mA + 8;
            const float v0 = (acc[i][j][0] + bv0) * scale;
            const float v1 = (acc[i][j][1] + bv1) * scale;
            const float v2 = (acc[i][j][2] + bv0) * scale;
            const float v3 = (acc[i][j][3] + bv1) * scale;
            if (mode == 0) {
                const int h = n >> 6, dkp = (n & 63) >> 1;
                const int bA = mA >> 11, sA = mA & (S_LEN - 1);
                const int bB = mB >> 11, sB = mB & (S_LEN - 1);
                uint32_t hh, ll;
                split_bf16x2(v0, v1, hh, ll);
                const size_t iA = ((size_t)(bA * NH + h) * S_LEN + sA) * PAIRS + dkp;
                dsth[iA] = hh; dstl[iA] = ll;
                split_bf16x2(v2, v3, hh, ll);
                const size_t iB = ((size_t)(bB * NH + h) * S_LEN + sB) * PAIRS + dkp;
                dsth[iB] = hh; dstl[iB] = ll;
            } else {
                *(float2*)&outp[(size_t)mA * D_MODEL + n] = make_float2(v0, v1);
                *(float2*)&outp[(size_t)mB * D_MODEL + n] = make_float2(v2, v3);
            }
        }
    }
}

// ===========================================================================
// 3xBF16 flash attention, R17: WIDE WARP TILES — 32 q-rows per warp.
//   QTILE 128, 4 warps, 128 threads/CTA, 2 CTAs/SM (110,592 B smem each).
//   Each K/V ldmatrix now feeds 2 m-tiles of MMAs -> per-SM LDSM traffic
//   per chunk drops 576KB -> 320KB (was the binding resource at 128 B/cyc).
//   Direct P-fragments (R16), online softmax, double-buffered cp.async.
//
// SMEM (u32 offsets, rows 36 u32 = 144 B):
//   Q_H 0 [128][36]  Q_L 4608
//   K_H(b) 9216+b*2304   K_L(b) 13824+b*2304
//   V_H(b) 18432+b*2304  V_L(b) 23040+b*2304
// Total 27648 u32 = 110,592 B
// ===========================================================================
#define S_Q_H 0
#define S_Q_L 4608
#define S_K_H(b) (9216  + (b) * 2304)
#define S_K_L(b) (13824 + (b) * 2304)
#define S_V_H(b) (18432 + (b) * 2304)
#define S_V_L(b) (23040 + (b) * 2304)
#define NCHUNK (S_LEN / 64)
#define QTILE  128
#define ATHREADS 128

__global__ __launch_bounds__(ATHREADS, 2) void attn_mma()
{
    extern __shared__ __align__(16) uint32_t sm[];
    const uint32_t sb = smem_u32(sm);

    const int tid = threadIdx.x;
    const int wid = tid >> 5, lid = tid & 31;
    const int bh = blockIdx.y;
    const int q0 = blockIdx.x * QTILE;
    const int qr = wid * 32;                  // 32 rows per warp
    const int g = lid >> 2, tg = lid & 3;

    const uint32_t* Qh = g_Qh + ((size_t)bh * S_LEN + q0) * PAIRS;
    const uint32_t* Ql = g_Ql + ((size_t)bh * S_LEN + q0) * PAIRS;
    const uint32_t* Kh = g_Kh + (size_t)bh * S_LEN * PAIRS;
    const uint32_t* Kl = g_Kl + (size_t)bh * S_LEN * PAIRS;
    const uint32_t* Vh = g_Vh + (size_t)bh * S_LEN * PAIRS;
    const uint32_t* Vl = g_Vl + (size_t)bh * S_LEN * PAIRS;

    // K/V chunk loader: 2048 x 16B over 128 threads = 16 per thread
    auto load_kv = [&](int buf, int kt) {
        const size_t base = (size_t)kt * 64 * PAIRS;
#pragma unroll
        for (int t = 0; t < 16; t++) {
            const int f = tid + ATHREADS * t;
            const int plane = f >> 9;
            const int rem = f & 511;
            const int r = rem >> 3, cc = rem & 7;
            const uint32_t* src;
            uint32_t dst;
            const size_t so = base + (size_t)r * PAIRS + cc * 4;
            if (plane == 0)      { src = Kh + so; dst = (uint32_t)S_K_H(buf); }
            else if (plane == 1) { src = Kl + so; dst = (uint32_t)S_K_L(buf); }
            else if (plane == 2) { src = Vh + so; dst = (uint32_t)S_V_H(buf); }
            else                 { src = Vl + so; dst = (uint32_t)S_V_L(buf); }
            cp_async16(sb + (dst + (uint32_t)(r * 36 + cc * 4)) * 4u, src);
        }
    };

    // Prologue: Q (2 planes x 128 rows x 8 = 2048) + KV chunk 0
#pragma unroll
    for (int t = 0; t < 16; t++) {
        const int f = tid + ATHREADS * t;
        const int plane = f >> 10;
        const int rem = f & 1023;
        const int r = rem >> 3, cc = rem & 7;
        const uint32_t* src = (plane ? Ql : Qh) + (size_t)r * PAIRS + cc * 4;
        const uint32_t dst = (uint32_t)(plane ? S_Q_L : S_Q_H) + (uint32_t)(r * 36 + cc * 4);
        cp_async16(sb + dst * 4u, src);
    }
    load_kv(0, 0);
    cp_commit();
    cp_wait<0>();
    __syncthreads();

    load_kv(1, 1);
    cp_commit();

    float mm[2][2], ll[2][2];
#pragma unroll
    for (int i = 0; i < 2; i++) {
        mm[i][0] = -1e30f; mm[i][1] = -1e30f;
        ll[i][0] = 0.0f;   ll[i][1] = 0.0f;
    }
    float o[2][8][4];
#pragma unroll
    for (int i = 0; i < 2; i++)
#pragma unroll
        for (int nt = 0; nt < 8; nt++)
#pragma unroll
            for (int e = 0; e < 4; e++) o[i][nt][e] = 0.0f;

    // Per-tile Q row base addresses (tile i covers rows qr+i*16 .. +15)
    uint32_t qbH[2], qbL[2];
#pragma unroll
    for (int i = 0; i < 2; i++) {
        const uint32_t rb = (uint32_t)(qr + i * 16 + (lid & 15)) * 144u
                          + (uint32_t)((lid >> 4) * 16);
        qbH[i] = sb + (uint32_t)S_Q_H * 4u + rb;
        qbL[i] = sb + (uint32_t)S_Q_L * 4u + rb;
    }

    for (int kt = 0; kt < NCHUNK; kt++) {
        const int buf = kt & 1;

        // ---- S = Q K^T: K frags shared across both m-tiles ----
        float s[2][8][4];
#pragma unroll
        for (int i = 0; i < 2; i++)
#pragma unroll
            for (int nt = 0; nt < 8; nt++)
#pragma unroll
                for (int e = 0; e < 4; e++) s[i][nt][e] = 0.0f;

        const uint32_t khb = sb + (uint32_t)S_K_H(buf) * 4u;
        const uint32_t klb = sb + (uint32_t)S_K_L(buf) * 4u;
        const uint32_t kroff = (uint32_t)(((lid >> 4) & 1) * 8 + (lid & 7)) * 144u
                             + (uint32_t)(((lid >> 3) & 1) * 16);
#pragma unroll
        for (int kc = 0; kc < 4; kc++) {
            uint32_t aH[2][4], aL[2][4];
#pragma unroll
            for (int i = 0; i < 2; i++) {
                ldsm_x4(aH[i], qbH[i] + kc * 32);
                ldsm_x4(aL[i], qbL[i] + kc * 32);
            }
#pragma unroll
            for (int ntp = 0; ntp < 4; ntp++) {
                const uint32_t ro = (uint32_t)(ntp * 16) * 144u + kroff + kc * 32;
                uint32_t rH[4], rL[4];
                ldsm_x4(rH, khb + ro);
                ldsm_x4(rL, klb + ro);
#pragma unroll
                for (int i = 0; i < 2; i++) {
                    mma_bf16(s[i][ntp * 2],     aH[i], &rH[0]);
                    mma_bf16(s[i][ntp * 2],     aL[i], &rH[0]);
                    mma_bf16(s[i][ntp * 2],     aH[i], &rL[0]);
                    mma_bf16(s[i][ntp * 2 + 1], aH[i], &rH[2]);
                    mma_bf16(s[i][ntp * 2 + 1], aL[i], &rH[2]);
                    mma_bf16(s[i][ntp * 2 + 1], aH[i], &rL[2]);
                }
            }
        }

        // ---- online softmax (per tile, rows g and g+8) ----
        uint32_t pH[2][8][2], pL[2][8][2];
#pragma unroll
        for (int i = 0; i < 2; i++) {
            float mx0 = -1e30f, mx1 = -1e30f;
#pragma unroll
            for (int nt = 0; nt < 8; nt++) {
                mx0 = fmaxf(mx0, fmaxf(s[i][nt][0], s[i][nt][1]));
                mx1 = fmaxf(mx1, fmaxf(s[i][nt][2], s[i][nt][3]));
            }
            mx0 = fmaxf(mx0, __shfl_xor_sync(0xffffffffu, mx0, 1));
            mx0 = fmaxf(mx0, __shfl_xor_sync(0xffffffffu, mx0, 2));
            mx1 = fmaxf(mx1, __shfl_xor_sync(0xffffffffu, mx1, 1));
            mx1 = fmaxf(mx1, __shfl_xor_sync(0xffffffffu, mx1, 2));
            const float nm0 = fmaxf(mm[i][0], mx0), nm1 = fmaxf(mm[i][1], mx1);
            const float al0 = __expf(mm[i][0] - nm0), al1 = __expf(mm[i][1] - nm1);
            mm[i][0] = nm0; mm[i][1] = nm1;
            float sum0 = 0.0f, sum1 = 0.0f;
#pragma unroll
            for (int nt = 0; nt < 8; nt++) {
                s[i][nt][0] = __expf(s[i][nt][0] - nm0);
                s[i][nt][1] = __expf(s[i][nt][1] - nm0);
                s[i][nt][2] = __expf(s[i][nt][2] - nm1);
                s[i][nt][3] = __expf(s[i][nt][3] - nm1);
                sum0 += s[i][nt][0] + s[i][nt][1];
                sum1 += s[i][nt][2] + s[i][nt][3];
            }
            sum0 += __shfl_xor_sync(0xffffffffu, sum0, 1);
            sum0 += __shfl_xor_sync(0xffffffffu, sum0, 2);
            sum1 += __shfl_xor_sync(0xffffffffu, sum1, 1);
            sum1 += __shfl_xor_sync(0xffffffffu, sum1, 2);
            ll[i][0] = ll[i][0] * al0 + sum0;
            ll[i][1] = ll[i][1] * al1 + sum1;
#pragma unroll
            for (int nt = 0; nt < 8; nt++) {
                o[i][nt][0] *= al0; o[i][nt][1] *= al0;
                o[i][nt][2] *= al1; o[i][nt][3] *= al1;
            }
            // direct P-fragment conversion (registers only)
#pragma unroll
            for (int nt = 0; nt < 8; nt++) {
                split_bf16x2(s[i][nt][0], s[i][nt][1], pH[i][nt][0], pL[i][nt][0]);
                split_bf16x2(s[i][nt][2], s[i][nt][3], pH[i][nt][1], pL[i][nt][1]);
            }
        }

        // ---- O += P V: V frags shared across both m-tiles ----
        const uint32_t vb_h = sb + (uint32_t)S_V_H(buf) * 4u;
        const uint32_t vb_l = sb + (uint32_t)S_V_L(buf) * 4u;
#pragma unroll
        for (int kc = 0; kc < 4; kc++) {
            uint32_t aH[2][4], aL[2][4];
#pragma unroll
            for (int i = 0; i < 2; i++) {
                aH[i][0] = pH[i][2 * kc][0];     aL[i][0] = pL[i][2 * kc][0];
                aH[i][1] = pH[i][2 * kc][1];     aL[i][1] = pL[i][2 * kc][1];
                aH[i][2] = pH[i][2 * kc + 1][0]; aL[i][2] = pL[i][2 * kc + 1][0];
                aH[i][3] = pH[i][2 * kc + 1][1]; aL[i][3] = pL[i][2 * kc + 1][1];
            }
            const uint32_t vrow = (uint32_t)(kc * 16 + (lid & 15)) * 144u
                                + (uint32_t)((lid >> 4) * 16);
#pragma unroll
            for (int ntp = 0; ntp < 4; ntp++) {
                uint32_t rH[4], rL[4];
                ldsm_x4_trans(rH, vb_h + vrow + ntp * 32);
                ldsm_x4_trans(rL, vb_l + vrow + ntp * 32);
#pragma unroll
                for (int i = 0; i < 2; i++) {
                    mma_bf16(o[i][ntp * 2],     aH[i], &rH[0]);
                    mma_bf16(o[i][ntp * 2],     aL[i], &rH[0]);
                    mma_bf16(o[i][ntp * 2],     aH[i], &rL[0]);
                    mma_bf16(o[i][ntp * 2 + 1], aH[i], &rH[2]);
                    mma_bf16(o[i][ntp * 2 + 1], aL[i], &rH[2]);
                    mma_bf16(o[i][ntp * 2 + 1], aH[i], &rL[2]);
                }
            }
        }

        // ---- pipeline tail ----
        if (kt + 1 < NCHUNK) {
            cp_wait<0>();
            __syncthreads();
            if (kt + 2 < NCHUNK) {
                load_kv(buf, kt + 2);
                cp_commit();
            }
        }
    }

    // ---- normalize + write pre-split merged-head O planes ----
    const int b = bh >> 3, h = bh & 7;
#pragma unroll
    for (int i = 0; i < 2; i++) {
        const float inv0 = 1.0f / ll[i][0], inv1 = 1.0f / ll[i][1];
        const int row0 = q0 + qr + i * 16 + g, row1 = row0 + 8;
#pragma unroll
        for (int nt = 0; nt < 8; nt++) {
            const int cp = h * 32 + nt * 4 + tg;
            uint32_t hh, llv;
            split_bf16x2(o[i][nt][0] * inv0, o[i][nt][1] * inv0, hh, llv);
            g_Oh[(size_t)(b * S_LEN + row0) * DPAIRS + cp] = hh;
            g_Ol[(size_t)(b * S_LEN + row0) * DPAIRS + cp] = llv;
            split_bf16x2(o[i][nt][2] * inv1, o[i][nt][3] * inv1, hh, llv);
            g_Oh[(size_t)(b * S_LEN + row1) * DPAIRS + cp] = hh;
            g_Ol[(size_t)(b * S_LEN + row1) * DPAIRS + cp] = llv;
        }
    }
}

// ---------------------------------------------------------------------------
extern "C" void kernel_launch(void* const* d_in, const int* in_sizes, int n_in,
                              void* d_out, int out_size)
{
    const float* q   = (const float*)d_in[0];
    const float* v   = (const float*)d_in[1];
    const float* k   = (const float*)d_in[2];
    const float* w_q = (const float*)d_in[3];
    const float* b_q = (const float*)d_in[4];
    const float* w_k = (const float*)d_in[5];
    const float* b_k = (const float*)d_in[6];
    const float* w_v = (const float*)d_in[7];
    const float* b_v = (const float*)d_in[8];
    const float* w_o = (const float*)d_in[9];
    const float* b_o = (const float*)d_in[10];
    float* out = (float*)d_out;

    const int gemm_smem = 2 * GBUF * 4;   // 81,920 B
    const int attn_smem = 27648 * 4;      // 110,592 B (2 CTAs/SM)
    cudaFuncSetAttribute(bf16_gemm, cudaFuncAttributeMaxDynamicSharedMemorySize,
                         gemm_smem);
    cudaFuncSetAttribute(attn_mma, cudaFuncAttributeMaxDynamicSharedMemorySize,
                         attn_smem);

    // 0) Pre-split all inputs to bf16 hi/lo planes
    split_inputs<<<dim3(MROWS * DPAIRS / 256, 7), 256>>>(q, k, v, w_q, w_k, w_v, w_o);
    // 1) Q/K/V projections (R14 GEMM, unchanged)
    bf16_gemm<<<dim3(D_MODEL / 128, MROWS / 128, 3), 512, gemm_smem>>>(
        b_q, b_k, b_v, nullptr, 0);
    // 2) Flash attention (32 rows/warp, 2 CTAs/SM)
    attn_mma<<<dim3(S_LEN / QTILE, BHCNT), ATHREADS, attn_smem>>>();
    // 3) Output projection (R14 GEMM, unchanged)
    bf16_gemm<<<dim3(D_MODEL / 128, MROWS / 128, 1), 512, gemm_smem>>>(
        b_o, nullptr, nullptr, out, 1);
}